// round 4
// baseline (speedup 1.0000x reference)
#include <cuda_runtime.h>
#include <cuda_bf16.h>
#include <math.h>

#define Bb 32
#define Ss 512
#define Hh 1024
#define Mm 8
#define NTOK (Bb * Ss)       // 16384
#define NSPAN (NTOK * Mm)    // 131072
#define TOPK 4915            // int(0.3 * B * S)
#define NBIN 65536
#define NCHUNK 1024
#define TIE_CAP 16384
#define CF_BLOCKS 148
#define CF_THREADS 256

// ---------------- device scratch ----------------
__device__ float g_query[Hh];
__device__ float g_e[NTOK];
__device__ float g_f[NTOK];
__device__ unsigned int g_keys[NSPAN];
__device__ int   g_hist16[NBIN];
__device__ unsigned char g_gbits[NTOK];   // bit l of byte t: span (t,l) is valid&&gold
__device__ float g_sp_sum;
__device__ int   g_gold_cnt;
__device__ int   g_valid_cnt;
__device__ unsigned int g_selP;
__device__ int   g_selRem;
__device__ int   g_right;
__device__ int   g_tiecnt;
__device__ int   g_done;
__device__ int   g_tie[TIE_CAP];

__device__ __forceinline__ float warpReduceF(float v) {
    #pragma unroll
    for (int o = 16; o; o >>= 1) v += __shfl_xor_sync(0xffffffffu, v, o);
    return v;
}
__device__ __forceinline__ int warpReduceI(int v) {
    #pragma unroll
    for (int o = 16; o; o >>= 1) v += __shfl_xor_sync(0xffffffffu, v, o);
    return v;
}

// ---------------- kernel 1: query = w_in @ term_weight + b_in; init state ----------------
__global__ void k_query(const float* __restrict__ w_in,
                        const float* __restrict__ tw,
                        const float* __restrict__ b_in) {
    int r = blockIdx.x;
    if (r == 0 && threadIdx.x == 0) {
        g_sp_sum = 0.0f; g_gold_cnt = 0; g_valid_cnt = 0;
        g_right = 0; g_tiecnt = 0; g_done = 0;
    }
    const float4* wr = reinterpret_cast<const float4*>(w_in + (size_t)r * Hh);
    const float4* t4 = reinterpret_cast<const float4*>(tw);
    int i = threadIdx.x;
    float4 a = wr[i];
    float4 b = t4[i];
    float acc = a.x * b.x + a.y * b.y + a.z * b.z + a.w * b.w;

    __shared__ float sh[8];
    float v = warpReduceF(acc);
    if ((threadIdx.x & 31) == 0) sh[threadIdx.x >> 5] = v;
    __syncthreads();
    if (threadIdx.x < 8) {
        float x = sh[threadIdx.x];
        #pragma unroll
        for (int o = 4; o; o >>= 1) x += __shfl_xor_sync(0xffu, x, o);
        if (threadIdx.x == 0) g_query[r] = x + b_in[r];
    }
}

// ---------------- kernel 2: e/f dot products; also zeroes hist ----------------
__global__ void k_ef(const float* __restrict__ hidden,
                     const float* __restrict__ score_w) {
    __shared__ float shq[Hh];
    __shared__ float shw[Hh];
    int gid = blockIdx.x * blockDim.x + threadIdx.x;
    if (gid < NBIN) g_hist16[gid] = 0;
    for (int i = threadIdx.x; i < Hh; i += blockDim.x) {
        shq[i] = g_query[i];
        shw[i] = score_w[i];
    }
    __syncthreads();

    int warp = threadIdx.x >> 5, lane = threadIdx.x & 31;
    int t = blockIdx.x * 8 + warp;
    const float4* hp = reinterpret_cast<const float4*>(hidden + (size_t)t * Hh);
    float e = 0.0f, f = 0.0f;
    #pragma unroll
    for (int c = 0; c < 8; c++) {
        int j = c * 32 + lane;
        float4 h = hp[j];
        int k = j * 4;
        e += h.x * shq[k] + h.y * shq[k + 1] + h.z * shq[k + 2] + h.w * shq[k + 3];
        f += h.x * shw[k] + h.y * shw[k + 1] + h.z * shw[k + 2] + h.w * shw[k + 3];
    }
    e = warpReduceF(e);
    f = warpReduceF(f);
    if (lane == 0) { g_e[t] = e; g_f[t] = f; }
}

// ---------------- kernel 3: scores, keys, gold bits, loss accum, 16-bit histogram ----------------
__global__ void k_scores(const float* __restrict__ score_b_p,
                         const int* __restrict__ seq_len,
                         const int* __restrict__ gold_mask) {
    int t = blockIdx.x * blockDim.x + threadIdx.x;
    float sp_local = 0.0f;
    int gold_local = 0, valid_local = 0;

    if (t < NTOK) {
        int b = t >> 9, s = t & (Ss - 1);
        int L = seq_len[b];
        float sb = score_b_p[0];

        // vector load of 8 gold_mask ints for this token
        const int4* gm4 = reinterpret_cast<const int4*>(gold_mask + t * Mm);
        int4 gm0 = gm4[0], gm1 = gm4[1];
        int gm[8] = {gm0.x, gm0.y, gm0.z, gm0.w, gm1.x, gm1.y, gm1.z, gm1.w};

        float m = -INFINITY, den = 0.0f, num = 0.0f;
        unsigned keys[8];
        unsigned char gb = 0;
        #pragma unroll
        for (int l = 0; l < Mm; l++) {
            int pos = s + l; if (pos > Ss - 1) pos = Ss - 1;
            float el = g_e[(b << 9) + pos];
            float fl = g_f[(b << 9) + pos];
            float mn = fmaxf(m, el);
            float sc = expf(m - mn);
            float we = expf(el - mn);
            den = den * sc + we;
            num = num * sc + we * fl;
            m = mn;
            float score = num / den + sb;

            unsigned key;
            if (s + l + 1 <= L) {
                unsigned u = __float_as_uint(score);
                key = u ^ ((u >> 31) ? 0xFFFFFFFFu : 0x80000000u);
                valid_local++;
                if (gm[l] == 0) {
                    gold_local++;
                    gb |= (unsigned char)(1u << l);
                    sp_local += fmaxf(-score, 0.0f) + log1pf(expf(-fabsf(score)));
                }
            } else {
                key = 0x007FFFFFu;  // flipped -inf
            }
            keys[l] = key;
            atomicAdd(&g_hist16[key >> 16], 1);
        }
        uint4* kp = reinterpret_cast<uint4*>(g_keys + t * Mm);
        kp[0] = make_uint4(keys[0], keys[1], keys[2], keys[3]);
        kp[1] = make_uint4(keys[4], keys[5], keys[6], keys[7]);
        g_gbits[t] = gb;
    }

    __shared__ float shf[8];
    __shared__ int shg[8], shv[8];
    float sp = warpReduceF(sp_local);
    int gd = warpReduceI(gold_local);
    int vd = warpReduceI(valid_local);
    if ((threadIdx.x & 31) == 0) {
        int w = threadIdx.x >> 5;
        shf[w] = sp; shg[w] = gd; shv[w] = vd;
    }
    __syncthreads();
    if (threadIdx.x == 0) {
        float S1 = 0.0f; int S2 = 0, S3 = 0;
        #pragma unroll
        for (int w = 0; w < 8; w++) { S1 += shf[w]; S2 += shg[w]; S3 += shv[w]; }
        atomicAdd(&g_sp_sum, S1);
        atomicAdd(&g_gold_cnt, S2);
        atomicAdd(&g_valid_cnt, S3);
    }
}

// ---------------- kernel 4: fused coalesced reduce + suffix scan + boundary walk ----------------
__global__ void k_select() {
    __shared__ int shh[2048];   // half-chunk sums: shh[j*32+w] = sum of bins [j*1024+w*32, +32)
    __shared__ int sch[NCHUNK];
    int tid = threadIdx.x;
    int warp = tid >> 5, lane = tid & 31;

    #pragma unroll 4
    for (int j = 0; j < 64; j++) {
        int v = g_hist16[j * 1024 + tid];   // fully coalesced
        v = warpReduceI(v);
        if (lane == 0) shh[j * 32 + warp] = v;
    }
    __syncthreads();
    // chunk c (64 bins): halves at shh[(c>>4)*32 + ((c&15)<<1)] and +1
    int csum = shh[(tid >> 4) * 32 + ((tid & 15) << 1)]
             + shh[(tid >> 4) * 32 + ((tid & 15) << 1) + 1];
    sch[tid] = csum;
    __syncthreads();
    for (int off = 1; off < NCHUNK; off <<= 1) {
        int v = (tid + off < NCHUNK) ? sch[tid + off] : 0;
        __syncthreads();
        sch[tid] += v;
        __syncthreads();
    }
    int incl = sch[tid];
    int above = incl - csum;
    if (above < TOPK && incl >= TOPK) {
        int base = tid * 64;
        int cum = above;
        for (int b = 63; b >= 0; b--) {
            int c = g_hist16[base + b];
            if (cum + c >= TOPK) {
                g_selP = (unsigned)(base + b);
                g_selRem = TOPK - cum;
                break;
            }
            cum += c;
        }
    }
}

// ---------------- kernel 5: count above threshold + ties; last block finalizes ----------------
__global__ void k_count_final(float* __restrict__ out) {
    unsigned P = g_selP;
    int tid = blockIdx.x * blockDim.x + threadIdx.x;
    int nthreads = gridDim.x * blockDim.x;
    int gg = 0;
    for (int i = tid; i < NSPAN; i += nthreads) {
        unsigned top = g_keys[i] >> 16;
        if (top > P) {
            if ((g_gbits[i >> 3] >> (i & 7)) & 1) gg++;
        } else if (top == P) {
            int pos = atomicAdd(&g_tiecnt, 1);
            if (pos < TIE_CAP) g_tie[pos] = i;
        }
    }
    gg = warpReduceI(gg);
    __shared__ int shc[8];
    __shared__ bool s_last;
    if ((threadIdx.x & 31) == 0) shc[threadIdx.x >> 5] = gg;
    __syncthreads();
    if (threadIdx.x == 0) {
        int S = 0;
        #pragma unroll
        for (int w = 0; w < (CF_THREADS >> 5); w++) S += shc[w];
        if (S) atomicAdd(&g_right, S);
        __threadfence();
        int d = atomicAdd(&g_done, 1);
        s_last = (d == (int)gridDim.x - 1);
    }
    __syncthreads();
    if (!s_last) return;

    // ---- final phase: only last block runs this ----
    int n = g_tiecnt; if (n > TIE_CAP) n = TIE_CAP;
    int rem = g_selRem;
    __shared__ int s_g;
    if (threadIdx.x == 0) s_g = 0;
    __syncthreads();

    int gtie = 0;
    for (int j = threadIdx.x; j < n; j += blockDim.x) {
        int ij = g_tie[j];
        unsigned kj = g_keys[ij];
        int rank = 0;
        for (int q = 0; q < n; q++) {
            int iq = g_tie[q];
            unsigned kq = g_keys[iq];
            if (kq > kj || (kq == kj && iq < ij)) rank++;
        }
        if (rank < rem) {
            if ((g_gbits[ij >> 3] >> (ij & 7)) & 1) gtie++;
        }
    }
    gtie = warpReduceI(gtie);
    if ((threadIdx.x & 31) == 0 && gtie) atomicAdd(&s_g, gtie);
    __syncthreads();

    if (threadIdx.x == 0) {
        int right = g_right + s_g;
        float nv = (float)g_valid_cnt;
        float loss = (g_sp_sum + 0.6931471805599453f * (float)(g_valid_cnt - g_gold_cnt)) / nv;
        out[0] = loss;
        out[1] = (float)right / (float)TOPK;
    }
}

// ---------------- launch ----------------
extern "C" void kernel_launch(void* const* d_in, const int* in_sizes, int n_in,
                              void* d_out, int out_size) {
    const float* hidden  = (const float*)d_in[0];
    const float* tw      = (const float*)d_in[1];
    const float* w_in    = (const float*)d_in[2];
    const float* b_in    = (const float*)d_in[3];
    const float* score_w = (const float*)d_in[4];
    const float* score_b = (const float*)d_in[5];
    const int*   seq_len = (const int*)d_in[6];
    const int*   gold    = (const int*)d_in[7];
    float* out = (float*)d_out;

    k_query      <<<Hh, 256>>>(w_in, tw, b_in);
    k_ef         <<<NTOK / 8, 256>>>(hidden, score_w);
    k_scores     <<<NTOK / 256, 256>>>(score_b, seq_len, gold);
    k_select     <<<1, 1024>>>();
    k_count_final<<<CF_BLOCKS, CF_THREADS>>>(out);
}

// round 5
// speedup vs baseline: 1.1977x; 1.1977x over previous
#include <cuda_runtime.h>
#include <cuda_bf16.h>
#include <math.h>

#define Bb 32
#define Ss 512
#define Hh 1024
#define Mm 8
#define NTOK (Bb * Ss)       // 16384
#define NSPAN (NTOK * Mm)    // 131072
#define TOPK 4915            // int(0.3 * B * S)
#define NBIN 65536
#define NCHUNK 1024          // 64 bins per chunk
#define TIE_CAP 16384
#define CF_BLOCKS 148
#define CF_THREADS 256

// ---------------- device scratch ----------------
__device__ float g_query[Hh];
__device__ float g_e[NTOK];
__device__ float g_f[NTOK];
__device__ unsigned int g_keys[NSPAN];
__device__ int   g_hist16[NBIN];
__device__ int   g_chunk[NCHUNK];
__device__ unsigned char g_gbits[NTOK];   // bit l of byte t: span (t,l) valid&&gold
__device__ float g_sp_sum;
__device__ int   g_gold_cnt;
__device__ int   g_valid_cnt;
__device__ unsigned int g_selP;
__device__ int   g_selRem;
__device__ int   g_right;
__device__ int   g_tiecnt;
__device__ int   g_done;
__device__ int   g_tie[TIE_CAP];

__device__ __forceinline__ float warpReduceF(float v) {
    #pragma unroll
    for (int o = 16; o; o >>= 1) v += __shfl_xor_sync(0xffffffffu, v, o);
    return v;
}
__device__ __forceinline__ int warpReduceI(int v) {
    #pragma unroll
    for (int o = 16; o; o >>= 1) v += __shfl_xor_sync(0xffffffffu, v, o);
    return v;
}

// ---------------- kernel 1: query = w_in @ term_weight + b_in; init state ----------------
__global__ void k_query(const float* __restrict__ w_in,
                        const float* __restrict__ tw,
                        const float* __restrict__ b_in) {
    int r = blockIdx.x;
    if (r == 0 && threadIdx.x == 0) {
        g_sp_sum = 0.0f; g_gold_cnt = 0; g_valid_cnt = 0;
        g_right = 0; g_tiecnt = 0; g_done = 0;
    }
    const float4* wr = reinterpret_cast<const float4*>(w_in + (size_t)r * Hh);
    const float4* t4 = reinterpret_cast<const float4*>(tw);
    int i = threadIdx.x;
    float4 a = wr[i];
    float4 b = t4[i];
    float acc = a.x * b.x + a.y * b.y + a.z * b.z + a.w * b.w;

    __shared__ float sh[8];
    float v = warpReduceF(acc);
    if ((threadIdx.x & 31) == 0) sh[threadIdx.x >> 5] = v;
    __syncthreads();
    if (threadIdx.x < 8) {
        float x = sh[threadIdx.x];
        #pragma unroll
        for (int o = 4; o; o >>= 1) x += __shfl_xor_sync(0xffu, x, o);
        if (threadIdx.x == 0) g_query[r] = x + b_in[r];
    }
}

// ---------------- kernel 2: e/f dot products; also zeroes hist ----------------
__global__ void k_ef(const float* __restrict__ hidden,
                     const float* __restrict__ score_w) {
    __shared__ float shq[Hh];
    __shared__ float shw[Hh];
    int gid = blockIdx.x * blockDim.x + threadIdx.x;
    if (gid < NBIN) g_hist16[gid] = 0;
    for (int i = threadIdx.x; i < Hh; i += blockDim.x) {
        shq[i] = g_query[i];
        shw[i] = score_w[i];
    }
    __syncthreads();

    int warp = threadIdx.x >> 5, lane = threadIdx.x & 31;
    int t = blockIdx.x * 8 + warp;
    const float4* hp = reinterpret_cast<const float4*>(hidden + (size_t)t * Hh);
    float e = 0.0f, f = 0.0f;
    #pragma unroll
    for (int c = 0; c < 8; c++) {
        int j = c * 32 + lane;
        float4 h = hp[j];
        int k = j * 4;
        e += h.x * shq[k] + h.y * shq[k + 1] + h.z * shq[k + 2] + h.w * shq[k + 3];
        f += h.x * shw[k] + h.y * shw[k + 1] + h.z * shw[k + 2] + h.w * shw[k + 3];
    }
    e = warpReduceF(e);
    f = warpReduceF(f);
    if (lane == 0) { g_e[t] = e; g_f[t] = f; }
}

// ---------------- kernel 3: scores, keys, gold bits, loss accum, 16-bit histogram ----------------
__global__ void k_scores(const float* __restrict__ score_b_p,
                         const int* __restrict__ seq_len,
                         const int* __restrict__ gold_mask) {
    int t = blockIdx.x * blockDim.x + threadIdx.x;
    float sp_local = 0.0f;
    int gold_local = 0, valid_local = 0;

    if (t < NTOK) {
        int b = t >> 9, s = t & (Ss - 1);
        int L = seq_len[b];
        float sb = score_b_p[0];

        const int4* gm4 = reinterpret_cast<const int4*>(gold_mask + t * Mm);
        int4 gm0 = gm4[0], gm1 = gm4[1];
        int gm[8] = {gm0.x, gm0.y, gm0.z, gm0.w, gm1.x, gm1.y, gm1.z, gm1.w};

        float m = -INFINITY, den = 0.0f, num = 0.0f;
        unsigned keys[8];
        unsigned char gb = 0;
        #pragma unroll
        for (int l = 0; l < Mm; l++) {
            int pos = s + l; if (pos > Ss - 1) pos = Ss - 1;
            float el = g_e[(b << 9) + pos];
            float fl = g_f[(b << 9) + pos];
            float mn = fmaxf(m, el);
            float sc = expf(m - mn);
            float we = expf(el - mn);
            den = den * sc + we;
            num = num * sc + we * fl;
            m = mn;
            float score = num / den + sb;

            unsigned key;
            if (s + l + 1 <= L) {
                unsigned u = __float_as_uint(score);
                key = u ^ ((u >> 31) ? 0xFFFFFFFFu : 0x80000000u);
                valid_local++;
                if (gm[l] == 0) {
                    gold_local++;
                    gb |= (unsigned char)(1u << l);
                    sp_local += fmaxf(-score, 0.0f) + log1pf(expf(-fabsf(score)));
                }
            } else {
                key = 0x007FFFFFu;  // flipped -inf
            }
            keys[l] = key;
            atomicAdd(&g_hist16[key >> 16], 1);
        }
        uint4* kp = reinterpret_cast<uint4*>(g_keys + t * Mm);
        kp[0] = make_uint4(keys[0], keys[1], keys[2], keys[3]);
        kp[1] = make_uint4(keys[4], keys[5], keys[6], keys[7]);
        g_gbits[t] = gb;
    }

    __shared__ float shf[8];
    __shared__ int shg[8], shv[8];
    float sp = warpReduceF(sp_local);
    int gd = warpReduceI(gold_local);
    int vd = warpReduceI(valid_local);
    if ((threadIdx.x & 31) == 0) {
        int w = threadIdx.x >> 5;
        shf[w] = sp; shg[w] = gd; shv[w] = vd;
    }
    __syncthreads();
    if (threadIdx.x == 0) {
        float S1 = 0.0f; int S2 = 0, S3 = 0;
        #pragma unroll
        for (int w = 0; w < 8; w++) { S1 += shf[w]; S2 += shg[w]; S3 += shv[w]; }
        atomicAdd(&g_sp_sum, S1);
        atomicAdd(&g_gold_cnt, S2);
        atomicAdd(&g_valid_cnt, S3);
    }
}

// ---------------- kernel 4a: grid-parallel vectorized reduce 65536 bins -> 1024 chunk sums ----
// 16 blocks x 1024 threads, int4 per thread. Chunk (64 bins) = 16 consecutive threads.
__global__ void k_reduce() {
    int tid = threadIdx.x;
    int gt = blockIdx.x * 1024 + tid;        // int4 index; covers 4 bins
    const int4* h4 = reinterpret_cast<const int4*>(g_hist16);
    int4 v = h4[gt];                         // fully coalesced
    int s = v.x + v.y + v.z + v.w;
    // reduce over 16-lane groups (one chunk per group)
    #pragma unroll
    for (int o = 8; o; o >>= 1) s += __shfl_xor_sync(0xffffffffu, s, o);
    if ((tid & 15) == 0) g_chunk[gt >> 4] = s;
}

// ---------------- kernel 4b: suffix scan 1024 chunks + shared-staged boundary walk --------
__global__ void k_scan2() {
    __shared__ int sh[NCHUNK];
    __shared__ int s_bchunk;
    __shared__ int s_above;
    __shared__ int s_bins[64];
    int tid = threadIdx.x;
    int csum = g_chunk[tid];
    sh[tid] = csum;
    __syncthreads();
    for (int off = 1; off < NCHUNK; off <<= 1) {
        int v = (tid + off < NCHUNK) ? sh[tid + off] : 0;
        __syncthreads();
        sh[tid] += v;
        __syncthreads();
    }
    int incl = sh[tid];
    int above = incl - csum;
    if (above < TOPK && incl >= TOPK) { s_bchunk = tid; s_above = above; }
    __syncthreads();
    int bc = s_bchunk;
    if (tid < 64) s_bins[tid] = g_hist16[bc * 64 + tid];  // coalesced stage
    __syncthreads();
    if (tid == 0) {
        int cum = s_above;
        for (int b = 63; b >= 0; b--) {
            int c = s_bins[b];
            if (cum + c >= TOPK) {
                g_selP = (unsigned)(bc * 64 + b);
                g_selRem = TOPK - cum;
                break;
            }
            cum += c;
        }
    }
}

// ---------------- kernel 5: count above threshold + ties; last block finalizes ----------------
__global__ void k_count_final(float* __restrict__ out) {
    unsigned P = g_selP;
    int tid = blockIdx.x * blockDim.x + threadIdx.x;
    int nthreads = gridDim.x * blockDim.x;
    int gg = 0;
    for (int i = tid; i < NSPAN; i += nthreads) {
        unsigned top = g_keys[i] >> 16;
        if (top > P) {
            if ((g_gbits[i >> 3] >> (i & 7)) & 1) gg++;
        } else if (top == P) {
            int pos = atomicAdd(&g_tiecnt, 1);
            if (pos < TIE_CAP) g_tie[pos] = i;
        }
    }
    gg = warpReduceI(gg);
    __shared__ int shc[8];
    __shared__ bool s_last;
    if ((threadIdx.x & 31) == 0) shc[threadIdx.x >> 5] = gg;
    __syncthreads();
    if (threadIdx.x == 0) {
        int S = 0;
        #pragma unroll
        for (int w = 0; w < (CF_THREADS >> 5); w++) S += shc[w];
        if (S) atomicAdd(&g_right, S);
        __threadfence();
        int d = atomicAdd(&g_done, 1);
        s_last = (d == (int)gridDim.x - 1);
    }
    __syncthreads();
    if (!s_last) return;

    // ---- final phase: only last block ----
    int n = g_tiecnt; if (n > TIE_CAP) n = TIE_CAP;
    int rem = g_selRem;
    __shared__ int s_g;
    if (threadIdx.x == 0) s_g = 0;
    __syncthreads();

    int gtie = 0;
    for (int j = threadIdx.x; j < n; j += blockDim.x) {
        int ij = g_tie[j];
        unsigned kj = g_keys[ij];
        int rank = 0;
        for (int q = 0; q < n; q++) {
            int iq = g_tie[q];
            unsigned kq = g_keys[iq];
            if (kq > kj || (kq == kj && iq < ij)) rank++;
        }
        if (rank < rem) {
            if ((g_gbits[ij >> 3] >> (ij & 7)) & 1) gtie++;
        }
    }
    gtie = warpReduceI(gtie);
    if ((threadIdx.x & 31) == 0 && gtie) atomicAdd(&s_g, gtie);
    __syncthreads();

    if (threadIdx.x == 0) {
        int right = g_right + s_g;
        float nv = (float)g_valid_cnt;
        float loss = (g_sp_sum + 0.6931471805599453f * (float)(g_valid_cnt - g_gold_cnt)) / nv;
        out[0] = loss;
        out[1] = (float)right / (float)TOPK;
    }
}

// ---------------- launch ----------------
extern "C" void kernel_launch(void* const* d_in, const int* in_sizes, int n_in,
                              void* d_out, int out_size) {
    const float* hidden  = (const float*)d_in[0];
    const float* tw      = (const float*)d_in[1];
    const float* w_in    = (const float*)d_in[2];
    const float* b_in    = (const float*)d_in[3];
    const float* score_w = (const float*)d_in[4];
    const float* score_b = (const float*)d_in[5];
    const int*   seq_len = (const int*)d_in[6];
    const int*   gold    = (const int*)d_in[7];
    float* out = (float*)d_out;

    k_query      <<<Hh, 256>>>(w_in, tw, b_in);
    k_ef         <<<NTOK / 8, 256>>>(hidden, score_w);
    k_scores     <<<NTOK / 256, 256>>>(score_b, seq_len, gold);
    k_reduce     <<<16, 1024>>>();
    k_scan2      <<<1, 1024>>>();
    k_count_final<<<CF_BLOCKS, CF_THREADS>>>(out);
}